// round 16
// baseline (speedup 1.0000x reference)
#include <cuda_runtime.h>
#include <math.h>

#define FULLMASK 0xffffffffu
#define AMASK    0x0000ffffu
#define PI_F 3.14159265358979323846f

#define B_SZ 1024
#define NANT 16
#define TT   512
#define HH   32
#define MSRC 3
#define NANG 360
#define NNOISE 13
#define MSTR 17

// ------------------- device scratch (no allocations allowed) -------------------
__device__ float  g_bn_scale[TT];
__device__ float  g_bn_shift[TT];
__device__ float  g_h[B_SZ * HH];
__device__ float  g_Rx[B_SZ * 512];
__device__ float2 g_Un[B_SZ * NNOISE * NANT];   // [b][k][n]
__device__ float2 g_CA[NANG * NANT];            // conj(steering) [a][n]
__device__ float  g_spec[B_SZ * NANG];

// ------------------- complex helpers -------------------
__device__ __forceinline__ float2 cadd(float2 a, float2 b){ return make_float2(a.x+b.x, a.y+b.y); }
__device__ __forceinline__ float2 csub(float2 a, float2 b){ return make_float2(a.x-b.x, a.y-b.y); }
__device__ __forceinline__ float2 cmul(float2 a, float2 b){ return make_float2(a.x*b.x-a.y*b.y, a.x*b.y+a.y*b.x); }
__device__ __forceinline__ float2 cmulj(float2 a, float2 b){ return make_float2(a.x*b.x+a.y*b.y, a.y*b.x-a.x*b.y); } // a*conj(b)
__device__ __forceinline__ float2 cscale(float2 a, float s){ return make_float2(a.x*s, a.y*s); }
__device__ __forceinline__ float  cabs2(float2 a){ return a.x*a.x + a.y*a.y; }
__device__ __forceinline__ float  cabs1(float2 a){ return fabsf(a.x) + fabsf(a.y); }
__device__ __forceinline__ float2 cdivc(float2 a, float2 b){
  float inv = 1.f/(b.x*b.x + b.y*b.y);
  return make_float2((a.x*b.x + a.y*b.y)*inv, (a.y*b.x - a.x*b.y)*inv);
}
__device__ __forceinline__ float2 csqrtc(float2 z){
  float r = sqrtf(z.x*z.x + z.y*z.y);
  if (r <= 0.f) return make_float2(0.f, 0.f);
  float t = sqrtf(0.5f*(r + fabsf(z.x)));
  if (z.x >= 0.f) return make_float2(t, z.y/(2.f*t));
  float im = (z.y >= 0.f) ? t : -t;
  return make_float2(z.y/(2.f*im), im);
}
__device__ __forceinline__ float sigm_(float x){ return 1.f/(1.f + __expf(-x)); }
__device__ __forceinline__ float tanh_(float x){
  float t = fminf(fmaxf(x, -15.f), 15.f);
  float e = __expf(2.f*t);
  return (e - 1.f)/(e + 1.f);
}

// ------------------- f32x2 packed math -------------------
__device__ __forceinline__ unsigned long long pk2(float lo, float hi){
  unsigned long long r;
  asm("mov.b64 %0, {%1, %2};" : "=l"(r) : "f"(lo), "f"(hi));
  return r;
}
__device__ __forceinline__ void upk2(unsigned long long p, float& lo, float& hi){
  asm("mov.b64 {%0, %1}, %2;" : "=f"(lo), "=f"(hi) : "l"(p));
}
__device__ __forceinline__ unsigned long long fma2_(unsigned long long a, unsigned long long b, unsigned long long c){
  unsigned long long d;
  asm("fma.rn.f32x2 %0, %1, %2, %3;" : "=l"(d) : "l"(a), "l"(b), "l"(c));
  return d;
}

// =============================================================================
// K1: per-timestep BatchNorm statistics. grid=512, block=256.
// =============================================================================
__global__ void bn_stats_kernel(const float* __restrict__ Xr, const float* __restrict__ Xi,
                                const float* __restrict__ bn_w, const float* __restrict__ bn_b) {
  int t = blockIdx.x;
  int a = t >> 4;
  const float* src = (a < NANT) ? (Xr + (size_t)a*TT) : (Xi + (size_t)(a-NANT)*TT);
  int off = (t & 15) << 5;
  float s = 0.f, s2 = 0.f;
  for (int idx = threadIdx.x; idx < B_SZ*HH; idx += blockDim.x) {
    float v = src[((size_t)(idx >> 5)) * (NANT*TT) + off + (idx & 31)];
    s += v; s2 += v*v;
  }
  for (int o = 16; o; o >>= 1) { s += __shfl_xor_sync(FULLMASK, s, o); s2 += __shfl_xor_sync(FULLMASK, s2, o); }
  __shared__ float as_[8], as2_[8];
  int wid = threadIdx.x >> 5;
  if ((threadIdx.x & 31) == 0) { as_[wid] = s; as2_[wid] = s2; }
  __syncthreads();
  if (threadIdx.x == 0) {
    float S = 0.f, S2 = 0.f;
    int nw = blockDim.x >> 5;
    for (int i = 0; i < nw; i++) { S += as_[i]; S2 += as2_[i]; }
    const float invN = 1.f / (float)(B_SZ*HH);
    float mean = S * invN;
    float var  = fmaxf(S2 * invN - mean*mean, 0.f);
    float sc = bn_w[t] * rsqrtf(var + 1e-5f);
    g_bn_scale[t] = sc;
    g_bn_shift[t] = bn_b[t] - mean*sc;
  }
}

// =============================================================================
// K2: steering matrix conj(A)[a][n] = exp(+i * pi * n * sin(angle_a))
// =============================================================================
__global__ void steer_kernel() {
  int idx = blockIdx.x * blockDim.x + threadIdx.x;
  if (idx >= NANG*NANT) return;
  int a = idx >> 4, n = idx & 15;
  float ang = -0.5f*PI_F + (float)a * (PI_F / (float)(NANG-1));
  float ph = PI_F * (float)n * sinf(ang);
  g_CA[idx] = make_float2(cosf(ph), sinf(ph));
}

// =============================================================================
// K3: GRU. ONE WARP PER BLOCK (full residency in one wave). lane = hidden unit.
// f32x2-packed gates. grid=1024, block=32.
// =============================================================================
__global__ void __launch_bounds__(32) gru_kernel(
    const float* __restrict__ Xr, const float* __restrict__ Xi,
    const float* __restrict__ Wih, const float* __restrict__ Whh,
    const float* __restrict__ bih, const float* __restrict__ bhh) {
  int b = blockIdx.x;
  int j = threadIdx.x;

  unsigned long long wvr[32], wvz[32], wvn[32];
#pragma unroll
  for (int k = 0; k < 32; k++) {
    wvr[k] = pk2(Wih[(j      )*32 + k], Whh[(j      )*32 + k]);
    wvz[k] = pk2(Wih[(j + 32 )*32 + k], Whh[(j + 32 )*32 + k]);
    wvn[k] = pk2(Wih[(j + 64 )*32 + k], Whh[(j + 64 )*32 + k]);
  }
  unsigned long long b_r = pk2(bih[j],    bhh[j]);
  unsigned long long b_z = pk2(bih[32+j], bhh[32+j]);
  unsigned long long b_n = pk2(bih[64+j], bhh[64+j]);

  __shared__ float sc_[TT], sh_[TT];
  for (int t = threadIdx.x; t < TT; t += 32) { sc_[t] = g_bn_scale[t]; sh_[t] = g_bn_shift[t]; }
  __syncwarp();

  const float* Xbr = Xr + (size_t)b * (NANT*TT);
  const float* Xbi = Xi + (size_t)b * (NANT*TT);
  float h = 0.f;
  for (int t = 0; t < TT; t++) {
    int a = t >> 4;
    const float* src = (a < NANT) ? (Xbr + a*TT) : (Xbi + (a-NANT)*TT);
    float xv = src[((t & 15) << 5) + j];
    xv = xv * sc_[t] + sh_[t];
    unsigned long long ar = b_r, az = b_z, an = b_n;
#pragma unroll
    for (int k = 0; k < 32; k++) {
      float xk = __shfl_sync(FULLMASK, xv, k);
      float hk = __shfl_sync(FULLMASK, h, k);
      unsigned long long xh = pk2(xk, hk);
      ar = fma2_(wvr[k], xh, ar);
      az = fma2_(wvz[k], xh, az);
      an = fma2_(wvn[k], xh, an);
    }
    float air, ahr, aiz, ahz, ain, ahn;
    upk2(ar, air, ahr); upk2(az, aiz, ahz); upk2(an, ain, ahn);
    float r = sigm_(air + ahr);
    float z = sigm_(aiz + ahz);
    float n = tanh_(ain + r*ahn);
    h = (1.f - z)*n + z*h;
  }
  g_h[b*HH + j] = h;
}

// =============================================================================
// K4: Rx = h @ fc_W^T + fc_b. grid=(2,64): x = output half, y = 16-batch group.
// =============================================================================
__global__ void __launch_bounds__(256) fc_rx_kernel(const float* __restrict__ fcW,
                                                    const float* __restrict__ fcb) {
  __shared__ float fcWs[32 * 257];   // [k][i], padded
  __shared__ float hs[16 * 32];      // [bb][k]
  int tid = threadIdx.x;
  int i0 = blockIdx.x * 256;
  int bg = blockIdx.y * 16;

  for (int idx = tid; idx < 256*32; idx += 256) {
    int k = idx & 31, i = idx >> 5;
    fcWs[k*257 + i] = fcW[i0*32 + idx];
  }
  for (int idx = tid; idx < 16*32; idx += 256)
    hs[idx] = g_h[bg*32 + idx];
  __syncthreads();

  float w[32];
#pragma unroll
  for (int k = 0; k < 32; k++) w[k] = fcWs[k*257 + tid];
  float bias = fcb[i0 + tid];

  for (int bb = 0; bb < 16; bb++) {
    float acc = bias;
#pragma unroll
    for (int k = 0; k < 32; k++) acc += w[k] * hs[bb*32 + k];
    g_Rx[(size_t)(bg + bb)*512 + i0 + tid] = acc;
  }
}

// =============================================================================
// K5: batched complex non-Hermitian 16x16 eig. ONE WARP PER BLOCK (grid=1024,
// ~7KB smem -> 7 blocks/SM, full residency). Halves of the warp split Givens
// updates via shfl-exchange; Q rotations deferred per sweep. Ballot deflation.
// Exceptional shift every 8 iters, cap 300.
// =============================================================================
__global__ void __launch_bounds__(32) eig_kernel() {
  __shared__ float2 T[16*MSTR];
  __shared__ float2 Q[16*MSTR];
  __shared__ float2 Y[16*MSTR];
  __shared__ float2 V[16];
  __shared__ float4 rotG[16];
  __shared__ float  rotI[16];

  int lane = threadIdx.x;
  int l16 = lane & 15;
  int half = lane >> 4;
  int b = blockIdx.x;

  const float* Rx = g_Rx + (size_t)b * 512;

  // ---- load K, init Q = I ----
  for (int idx = lane; idx < 256; idx += 32) {
    int r = idx >> 4, c = idx & 15;
    T[r*MSTR + c] = make_float2(Rx[r*16 + c], Rx[256 + r*16 + c]);
    Q[r*MSTR + c] = make_float2((r == c) ? 1.f : 0.f, 0.f);
  }
  __syncwarp();

  // ---- Hessenberg reduction ----
  for (int j = 0; j < 14; j++) {
    float2 xr = make_float2(0.f, 0.f);
    if (l16 > j) xr = T[l16*MSTR + j];
    float nrm2 = cabs2(xr);
    for (int o = 8; o; o >>= 1) nrm2 += __shfl_xor_sync(FULLMASK, nrm2, o);
    if (nrm2 < 1e-30f) continue;
    float2 alpha;
    alpha.x = __shfl_sync(FULLMASK, xr.x, j+1);
    alpha.y = __shfl_sync(FULLMASK, xr.y, j+1);
    float an = sqrtf(cabs2(alpha));
    float2 ph = (an > 0.f) ? cscale(alpha, 1.f/an) : make_float2(1.f, 0.f);
    float nrm = sqrtf(nrm2);
    float2 ce1 = cscale(ph, nrm);
    if (l16 == j+1) xr = cadd(xr, ce1);
    if (lane < 16) V[lane] = (l16 > j) ? xr : make_float2(0.f, 0.f);
    float vv = (l16 > j) ? cabs2(xr) : 0.f;
    for (int o = 8; o; o >>= 1) vv += __shfl_xor_sync(FULLMASK, vv, o);
    float g = 2.f / vv;
    __syncwarp();

    // left: T[j+1.., c] -= g * v * (v^H T[j+1.., c]); rows striped by half
    {
      int c = l16;
      float2 s = make_float2(0.f, 0.f);
      for (int r = j+1; r < 16; r++) s = cadd(s, cmulj(T[r*MSTR + c], V[r]));
      float2 gs = cscale(s, g);
      __syncwarp();
      for (int r = j+1+half; r < 16; r += 2)
        T[r*MSTR + c] = csub(T[r*MSTR + c], cmul(V[r], gs));
    }
    __syncwarp();
    // right: half 0 -> T rows, half 1 -> Q rows (row-private)
    {
      int r = l16;
      float2* M = half ? Q : T;
      float2 s = make_float2(0.f, 0.f);
      for (int c = j+1; c < 16; c++) s = cadd(s, cmul(M[r*MSTR + c], V[c]));
      float2 gs = cscale(s, g);
      for (int c = j+1; c < 16; c++)
        M[r*MSTR + c] = csub(M[r*MSTR + c], cmulj(gs, V[c]));
    }
    __syncwarp();
  }

  // ---- shifted QR to Schur form ----
  const float EPSQ = 1e-5f;
  int hi = 15;
  int iter_at_hi = 0, total = 0;
  while (hi > 0 && total < 300) {
    // parallel deflation scan
    bool small = false;
    if (l16 >= 1 && l16 <= hi) {
      float sub = cabs1(T[l16*MSTR + (l16-1)]);
      float thr = EPSQ * (cabs1(T[(l16-1)*MSTR + (l16-1)]) + cabs1(T[l16*MSTR + l16])) + 1e-30f;
      small = (sub <= thr);
    }
    unsigned msk = __ballot_sync(FULLMASK, small) & 0xFFFFu;
    if (small && lane < 16) T[l16*MSTR + (l16-1)] = make_float2(0.f, 0.f);
    __syncwarp();
    int lo = msk ? (31 - __clz((int)msk)) : 0;
    if (lo == hi) { hi--; iter_at_hi = 0; continue; }
    iter_at_hi++; total++;

    // shift (uniform on all lanes)
    float2 tbb = T[hi*MSTR + hi];
    float2 mu;
    if (iter_at_hi % 8 == 0) {
      float es = cabs1(T[hi*MSTR + (hi-1)]);
      mu = make_float2(tbb.x + 0.75f*es, tbb.y);
    } else {
      float2 taa = T[(hi-1)*MSTR + (hi-1)];
      float2 tab = T[(hi-1)*MSTR + hi];
      float2 tba = T[hi*MSTR + (hi-1)];
      float2 p = cscale(csub(taa, tbb), 0.5f);
      float2 q = csqrtc(cadd(cmul(p, p), cmul(tab, tba)));
      float2 s1 = cadd(p, q), s2 = csub(p, q);
      float2 dd = (cabs2(s1) < cabs2(s2)) ? s1 : s2;
      mu = cadd(tbb, dd);
    }

    float2 ga = csub(T[lo*MSTR + lo], mu);
    float2 gb = T[(lo+1)*MSTR + lo];
    int nrot = hi - lo;
    for (int k = lo; k < hi; k++) {
      if (k > lo) { ga = T[k*MSTR + (k-1)]; gb = T[(k+1)*MSTR + (k-1)]; }
      float r2 = cabs2(ga) + cabs2(gb);
      float invr;
      if (r2 > 1e-37f) invr = rsqrtf(r2);
      else { ga = make_float2(1.f, 0.f); gb = make_float2(0.f, 0.f); invr = 1.f; }
      if (lane == 0) {
        rotG[k-lo] = make_float4(ga.x, ga.y, gb.x, gb.y);
        rotI[k-lo] = invr;
      }
      // left update: rows k (half0) / k+1 (half1), col = l16, shfl-exchange
      {
        int c = l16;
        float2 own = T[(k+half)*MSTR + c];
        float2 oth;
        oth.x = __shfl_xor_sync(FULLMASK, own.x, 16);
        oth.y = __shfl_xor_sync(FULLMASK, own.y, 16);
        float2 p  = half ? oth : own;   // row k
        float2 q2 = half ? own : oth;   // row k+1
        float2 outv;
        if (half == 0) outv = cscale(cadd(cmulj(p, ga), cmulj(q2, gb)), invr);
        else           outv = cscale(csub(cmul(ga, q2), cmul(gb, p)), invr);
        T[(k+half)*MSTR + c] = outv;
      }
      __syncwarp();
      // right update on T: cols k (half0) / k+1 (half1), row = l16
      {
        int r = l16;
        float2 own = T[r*MSTR + k + half];
        float2 oth;
        oth.x = __shfl_xor_sync(FULLMASK, own.x, 16);
        oth.y = __shfl_xor_sync(FULLMASK, own.y, 16);
        float2 u  = half ? oth : own;   // col k
        float2 v2 = half ? own : oth;   // col k+1
        float2 outv;
        if (half == 0) outv = cscale(cadd(cmul(u, ga), cmul(v2, gb)), invr);
        else           outv = cscale(csub(cmulj(v2, ga), cmulj(u, gb)), invr);
        T[r*MSTR + k + half] = outv;
      }
      __syncwarp();
    }
    // apply stored rotations to Q (register carry, row-private)
    if (lane < 16) {
      int r = l16;
      float2 u = Q[r*MSTR + lo];
      for (int kk = 0; kk < nrot; kk++) {
        float4 g4 = rotG[kk];
        float iv = rotI[kk];
        float2 ga2 = make_float2(g4.x, g4.y), gb2 = make_float2(g4.z, g4.w);
        float2 v2 = Q[r*MSTR + lo + kk + 1];
        Q[r*MSTR + lo + kk] = cscale(cadd(cmul(u, ga2), cmul(v2, gb2)), iv);
        u = cscale(csub(cmulj(v2, ga2), cmulj(u, gb2)), iv);
      }
      Q[r*MSTR + hi] = u;
    }
    __syncwarp();
  }
  __syncwarp();

  // ---- eigenvectors (lanes 0-15; lane k owns eigenvector k) ----
  if (lane < 16) {
    float2 lam = T[lane*MSTR + lane];
    for (int j2 = 0; j2 < 16; j2++)
      Y[j2*MSTR + lane] = make_float2((j2 == lane) ? 1.f : 0.f, 0.f);
    float lscale = cabs1(lam) + 1e-20f;
    for (int i = 14; i >= 0; i--) {
      if (lane > i) {
        float2 ssum = make_float2(0.f, 0.f);
        for (int j2 = i+1; j2 <= lane; j2++)
          ssum = cadd(ssum, cmul(T[i*MSTR + j2], Y[j2*MSTR + lane]));
        float2 den = csub(T[i*MSTR + i], lam);
        float dmin = 1.1920929e-07f * lscale;
        if (cabs2(den) < dmin*dmin) den = make_float2(dmin, 0.f);
        float2 val = cdivc(make_float2(-ssum.x, -ssum.y), den);
        if (cabs2(val) > 1e24f) {
          float scf = 1e-12f;
          for (int j2 = i+1; j2 <= lane; j2++) {
            float2 t2 = Y[j2*MSTR + lane];
            Y[j2*MSTR + lane] = cscale(t2, scf);
          }
          val = cscale(val, scf);
        }
        Y[i*MSTR + lane] = val;
      }
    }

    // v = Q * y  (only columns 0..k contribute), normalize
    float2 vout[16];
    float n2 = 0.f;
#pragma unroll
    for (int r = 0; r < 16; r++) {
      float2 acc = make_float2(0.f, 0.f);
      for (int j2 = 0; j2 <= lane; j2++)
        acc = cadd(acc, cmul(Q[r*MSTR + j2], Y[j2*MSTR + lane]));
      vout[r] = acc;
      n2 += cabs2(acc);
    }
    float invn = rsqrtf(fmaxf(n2, 1e-37f));

    // rank by |lambda| descending (ties: larger index first)
    float aw = cabs2(lam);
    int rank = 0;
    for (int j2 = 0; j2 < 16; j2++) {
      float awj = __shfl_sync(AMASK, aw, j2);
      if (awj > aw || (awj == aw && j2 > lane)) rank++;
    }
    if (rank >= MSRC) {
      float2* dst = g_Un + (size_t)b * (NNOISE*NANT) + (rank - MSRC) * NANT;
#pragma unroll
      for (int r = 0; r < 16; r++) dst[r] = cscale(vout[r], invn);
    }
  }
}

// =============================================================================
// K6: MUSIC spectrum. One block per batch element, block=128.
// =============================================================================
__global__ void spec_kernel() {
  int b = blockIdx.x;
  __shared__ float2 su[NNOISE * NANT];
  for (int i = threadIdx.x; i < NNOISE*NANT; i += blockDim.x)
    su[i] = g_Un[(size_t)b * (NNOISE*NANT) + i];
  __syncthreads();
  for (int a = threadIdx.x; a < NANG; a += blockDim.x) {
    float2 ca[16];
#pragma unroll
    for (int n = 0; n < 16; n++) ca[n] = g_CA[a*16 + n];
    float den = 0.f;
    for (int k = 0; k < NNOISE; k++) {
      float2 acc = make_float2(0.f, 0.f);
#pragma unroll
      for (int n = 0; n < 16; n++) acc = cadd(acc, cmul(ca[n], su[k*16 + n]));
      den += cabs2(acc);
    }
    g_spec[b*NANG + a] = 1.f / den;
  }
}

// =============================================================================
// K7: MLP head. One warp per batch element, fc1W staged in shared.
// =============================================================================
__global__ void __launch_bounds__(128) head_kernel(
    const float* __restrict__ fc1W, const float* __restrict__ fc1b,
    const float* __restrict__ fc2W, const float* __restrict__ fc2b,
    const float* __restrict__ fc3W, const float* __restrict__ fc3b,
    float* __restrict__ out) {
  __shared__ float w1s[32 * 361];   // [j][a], padded to 361
  for (int idx = threadIdx.x; idx < 32*NANG; idx += blockDim.x) {
    int j = idx / NANG, a = idx - j*NANG;
    w1s[j*361 + a] = fc1W[idx];
  }
  __syncthreads();

  int b = blockIdx.x * 4 + (threadIdx.x >> 5);
  int lane = threadIdx.x & 31;
  const float* sp = g_spec + (size_t)b * NANG;

  float acc = fc1b[lane];
  const float* wrow = w1s + lane*361;
  for (int a = 0; a < NANG; a++) acc += sp[a] * wrow[a];
  float h1 = fmaxf(acc, 0.f);

  float w2[32];
#pragma unroll
  for (int k = 0; k < 32; k++) w2[k] = fc2W[lane*32 + k];
  float b2 = fc2b[lane];

  float a2 = b2;
#pragma unroll
  for (int k = 0; k < 32; k++) a2 += w2[k] * __shfl_sync(FULLMASK, h1, k);
  float h2 = fmaxf(a2, 0.f);

  float a3 = b2;
#pragma unroll
  for (int k = 0; k < 32; k++) a3 += w2[k] * __shfl_sync(FULLMASK, h2, k);
  float h3 = fmaxf(a3, 0.f);

#pragma unroll
  for (int m = 0; m < MSRC; m++) {
    float p = fc3W[m*32 + lane] * h3;
    for (int o = 16; o; o >>= 1) p += __shfl_xor_sync(FULLMASK, p, o);
    if (lane == 0) out[b*MSRC + m] = p + fc3b[m];
  }
}

// =============================================================================
extern "C" void kernel_launch(void* const* d_in, const int* in_sizes, int n_in,
                              void* d_out, int out_size) {
  const float* Xr   = (const float*)d_in[0];
  const float* Xi   = (const float*)d_in[1];
  const float* bn_w = (const float*)d_in[2];
  const float* bn_b = (const float*)d_in[3];
  const float* Wih  = (const float*)d_in[4];
  const float* Whh  = (const float*)d_in[5];
  const float* bih  = (const float*)d_in[6];
  const float* bhh  = (const float*)d_in[7];
  const float* fcW  = (const float*)d_in[8];
  const float* fcb  = (const float*)d_in[9];
  const float* fc1W = (const float*)d_in[10];
  const float* fc1b = (const float*)d_in[11];
  const float* fc2W = (const float*)d_in[12];
  const float* fc2b = (const float*)d_in[13];
  const float* fc3W = (const float*)d_in[14];
  const float* fc3b = (const float*)d_in[15];
  float* out = (float*)d_out;

  bn_stats_kernel<<<TT, 256>>>(Xr, Xi, bn_w, bn_b);
  steer_kernel<<<(NANG*NANT + 255)/256, 256>>>();
  gru_kernel<<<B_SZ, 32>>>(Xr, Xi, Wih, Whh, bih, bhh);
  fc_rx_kernel<<<dim3(2,64), 256>>>(fcW, fcb);
  eig_kernel<<<B_SZ, 32>>>();
  spec_kernel<<<B_SZ, 128>>>();
  head_kernel<<<B_SZ/4, 128>>>(fc1W, fc1b, fc2W, fc2b, fc3W, fc3b, out);
}

// round 17
// speedup vs baseline: 1.0840x; 1.0840x over previous
#include <cuda_runtime.h>
#include <math.h>

#define FULLMASK 0xffffffffu
#define AMASK    0x0000ffffu
#define PI_F 3.14159265358979323846f

#define B_SZ 1024
#define NANT 16
#define TT   512
#define HH   32
#define MSRC 3
#define NANG 360
#define NNOISE 13
#define MSTR 17

// ------------------- device scratch (no allocations allowed) -------------------
__device__ float  g_bn_scale[TT];
__device__ float  g_bn_shift[TT];
__device__ float  g_h[B_SZ * HH];
__device__ float  g_Rx[B_SZ * 512];
__device__ float2 g_Un[B_SZ * NNOISE * NANT];   // [b][k][n]
__device__ float2 g_CA[NANG * NANT];            // conj(steering) [a][n]
__device__ float  g_spec[B_SZ * NANG];

// ------------------- complex helpers -------------------
__device__ __forceinline__ float2 cadd(float2 a, float2 b){ return make_float2(a.x+b.x, a.y+b.y); }
__device__ __forceinline__ float2 csub(float2 a, float2 b){ return make_float2(a.x-b.x, a.y-b.y); }
__device__ __forceinline__ float2 cmul(float2 a, float2 b){ return make_float2(a.x*b.x-a.y*b.y, a.x*b.y+a.y*b.x); }
__device__ __forceinline__ float2 cmulj(float2 a, float2 b){ return make_float2(a.x*b.x+a.y*b.y, a.y*b.x-a.x*b.y); } // a*conj(b)
__device__ __forceinline__ float2 cscale(float2 a, float s){ return make_float2(a.x*s, a.y*s); }
__device__ __forceinline__ float  cabs2(float2 a){ return a.x*a.x + a.y*a.y; }
__device__ __forceinline__ float  cabs1(float2 a){ return fabsf(a.x) + fabsf(a.y); }
__device__ __forceinline__ float2 cdivc(float2 a, float2 b){
  float inv = 1.f/(b.x*b.x + b.y*b.y);
  return make_float2((a.x*b.x + a.y*b.y)*inv, (a.y*b.x - a.x*b.y)*inv);
}
__device__ __forceinline__ float2 csqrtc(float2 z){
  float r = sqrtf(z.x*z.x + z.y*z.y);
  if (r <= 0.f) return make_float2(0.f, 0.f);
  float t = sqrtf(0.5f*(r + fabsf(z.x)));
  if (z.x >= 0.f) return make_float2(t, z.y/(2.f*t));
  float im = (z.y >= 0.f) ? t : -t;
  return make_float2(z.y/(2.f*im), im);
}
__device__ __forceinline__ float sigm_(float x){ return 1.f/(1.f + __expf(-x)); }
__device__ __forceinline__ float tanh_(float x){
  float t = fminf(fmaxf(x, -15.f), 15.f);
  float e = __expf(2.f*t);
  return (e - 1.f)/(e + 1.f);
}

// =============================================================================
// K1: per-timestep BatchNorm statistics. grid=512, block=256.
// =============================================================================
__global__ void bn_stats_kernel(const float* __restrict__ Xr, const float* __restrict__ Xi,
                                const float* __restrict__ bn_w, const float* __restrict__ bn_b) {
  int t = blockIdx.x;
  int a = t >> 4;
  const float* src = (a < NANT) ? (Xr + (size_t)a*TT) : (Xi + (size_t)(a-NANT)*TT);
  int off = (t & 15) << 5;
  float s = 0.f, s2 = 0.f;
  for (int idx = threadIdx.x; idx < B_SZ*HH; idx += blockDim.x) {
    float v = src[((size_t)(idx >> 5)) * (NANT*TT) + off + (idx & 31)];
    s += v; s2 += v*v;
  }
  for (int o = 16; o; o >>= 1) { s += __shfl_xor_sync(FULLMASK, s, o); s2 += __shfl_xor_sync(FULLMASK, s2, o); }
  __shared__ float as_[8], as2_[8];
  int wid = threadIdx.x >> 5;
  if ((threadIdx.x & 31) == 0) { as_[wid] = s; as2_[wid] = s2; }
  __syncthreads();
  if (threadIdx.x == 0) {
    float S = 0.f, S2 = 0.f;
    int nw = blockDim.x >> 5;
    for (int i = 0; i < nw; i++) { S += as_[i]; S2 += as2_[i]; }
    const float invN = 1.f / (float)(B_SZ*HH);
    float mean = S * invN;
    float var  = fmaxf(S2 * invN - mean*mean, 0.f);
    float sc = bn_w[t] * rsqrtf(var + 1e-5f);
    g_bn_scale[t] = sc;
    g_bn_shift[t] = bn_b[t] - mean*sc;
  }
}

// =============================================================================
// K2: steering matrix conj(A)[a][n] = exp(+i * pi * n * sin(angle_a))
// =============================================================================
__global__ void steer_kernel() {
  int idx = blockIdx.x * blockDim.x + threadIdx.x;
  if (idx >= NANG*NANT) return;
  int a = idx >> 4, n = idx & 15;
  float ang = -0.5f*PI_F + (float)a * (PI_F / (float)(NANG-1));
  float ph = PI_F * (float)n * sinf(ang);
  g_CA[idx] = make_float2(cosf(ph), sinf(ph));
}

// =============================================================================
// K3: GRU. One warp per batch element, lane = hidden unit. SCALAR weights:
// 192 float regs -- fits under the 255-reg cap with NO local-memory spills
// (the f32x2 variant needed 384 regs of weights and spilled).
// grid=256, block=128.
// =============================================================================
__global__ void __launch_bounds__(128, 1) gru_kernel(
    const float* __restrict__ Xr, const float* __restrict__ Xi,
    const float* __restrict__ Wih, const float* __restrict__ Whh,
    const float* __restrict__ bih, const float* __restrict__ bhh) {
  int b = blockIdx.x * 4 + (threadIdx.x >> 5);
  int j = threadIdx.x & 31;

  float wr[32], wz[32], wn[32], vr[32], vz[32], vn[32];
#pragma unroll
  for (int k = 0; k < 32; k++) {
    wr[k] = Wih[(j      )*32 + k];
    wz[k] = Wih[(j + 32 )*32 + k];
    wn[k] = Wih[(j + 64 )*32 + k];
    vr[k] = Whh[(j      )*32 + k];
    vz[k] = Whh[(j + 32 )*32 + k];
    vn[k] = Whh[(j + 64 )*32 + k];
  }
  float bir = bih[j], biz = bih[32+j], bin_ = bih[64+j];
  float bhr = bhh[j], bhz = bhh[32+j], bhn  = bhh[64+j];

  __shared__ float sc_[TT], sh_[TT];
  for (int t = threadIdx.x; t < TT; t += blockDim.x) { sc_[t] = g_bn_scale[t]; sh_[t] = g_bn_shift[t]; }
  __syncthreads();

  const float* Xbr = Xr + (size_t)b * (NANT*TT);
  const float* Xbi = Xi + (size_t)b * (NANT*TT);
  float h = 0.f;
  for (int t = 0; t < TT; t++) {
    int a = t >> 4;
    const float* src = (a < NANT) ? (Xbr + a*TT) : (Xbi + (a-NANT)*TT);
    float xv = src[((t & 15) << 5) + j];
    xv = xv * sc_[t] + sh_[t];
    float air = bir, aiz = biz, ain = bin_;
    float ahr = bhr, ahz = bhz, ahn = bhn;
#pragma unroll
    for (int k = 0; k < 32; k++) {
      float xk = __shfl_sync(FULLMASK, xv, k);
      float hk = __shfl_sync(FULLMASK, h, k);
      air += wr[k]*xk; aiz += wz[k]*xk; ain += wn[k]*xk;
      ahr += vr[k]*hk; ahz += vz[k]*hk; ahn += vn[k]*hk;
    }
    float r = sigm_(air + ahr);
    float z = sigm_(aiz + ahz);
    float n = tanh_(ain + r*ahn);
    h = (1.f - z)*n + z*h;
  }
  g_h[b*HH + j] = h;
}

// =============================================================================
// K4: Rx = h @ fc_W^T + fc_b. grid=(2,64): x = output half, y = 16-batch group.
// =============================================================================
__global__ void __launch_bounds__(256) fc_rx_kernel(const float* __restrict__ fcW,
                                                    const float* __restrict__ fcb) {
  __shared__ float fcWs[32 * 257];   // [k][i], padded
  __shared__ float hs[16 * 32];      // [bb][k]
  int tid = threadIdx.x;
  int i0 = blockIdx.x * 256;
  int bg = blockIdx.y * 16;

  for (int idx = tid; idx < 256*32; idx += 256) {
    int k = idx & 31, i = idx >> 5;
    fcWs[k*257 + i] = fcW[i0*32 + idx];
  }
  for (int idx = tid; idx < 16*32; idx += 256)
    hs[idx] = g_h[bg*32 + idx];
  __syncthreads();

  float w[32];
#pragma unroll
  for (int k = 0; k < 32; k++) w[k] = fcWs[k*257 + tid];
  float bias = fcb[i0 + tid];

  for (int bb = 0; bb < 16; bb++) {
    float acc = bias;
#pragma unroll
    for (int k = 0; k < 32; k++) acc += w[k] * hs[bb*32 + k];
    g_Rx[(size_t)(bg + bb)*512 + i0 + tid] = acc;
  }
}

// =============================================================================
// K5: batched complex non-Hermitian 16x16 eig. One warp per matrix, ALL 32
// lanes active: halves split the Givens updates via shfl-exchange; Q rotations
// deferred per sweep (register carry). Ballot deflation. Exceptional shift
// every 8 iters, cap 300. grid=256, block=128 (4 warps).
// =============================================================================
__global__ void __launch_bounds__(128) eig_kernel() {
  __shared__ float2 sT[4][16*MSTR];
  __shared__ float2 sQ[4][16*MSTR];
  __shared__ float2 sY[4][16*MSTR];
  __shared__ float2 sv[4][16];
  __shared__ float4 sG[4][16];
  __shared__ float  sI[4][16];

  int w = threadIdx.x >> 5;
  int lane = threadIdx.x & 31;
  int l16 = lane & 15;
  int half = lane >> 4;
  int b = blockIdx.x * 4 + w;

  float2* T = sT[w];
  float2* Q = sQ[w];
  float2* Y = sY[w];
  float2* V = sv[w];
  float4* rotG = sG[w];
  float*  rotI = sI[w];
  const float* Rx = g_Rx + (size_t)b * 512;

  // ---- load K, init Q = I ----
  for (int idx = lane; idx < 256; idx += 32) {
    int r = idx >> 4, c = idx & 15;
    T[r*MSTR + c] = make_float2(Rx[r*16 + c], Rx[256 + r*16 + c]);
    Q[r*MSTR + c] = make_float2((r == c) ? 1.f : 0.f, 0.f);
  }
  __syncwarp();

  // ---- Hessenberg reduction ----
  for (int j = 0; j < 14; j++) {
    float2 xr = make_float2(0.f, 0.f);
    if (l16 > j) xr = T[l16*MSTR + j];
    float nrm2 = cabs2(xr);
    for (int o = 8; o; o >>= 1) nrm2 += __shfl_xor_sync(FULLMASK, nrm2, o);
    if (nrm2 < 1e-30f) continue;
    float2 alpha;
    alpha.x = __shfl_sync(FULLMASK, xr.x, j+1);
    alpha.y = __shfl_sync(FULLMASK, xr.y, j+1);
    float an = sqrtf(cabs2(alpha));
    float2 ph = (an > 0.f) ? cscale(alpha, 1.f/an) : make_float2(1.f, 0.f);
    float nrm = sqrtf(nrm2);
    float2 ce1 = cscale(ph, nrm);
    if (l16 == j+1) xr = cadd(xr, ce1);
    if (lane < 16) V[lane] = (l16 > j) ? xr : make_float2(0.f, 0.f);
    float vv = (l16 > j) ? cabs2(xr) : 0.f;
    for (int o = 8; o; o >>= 1) vv += __shfl_xor_sync(FULLMASK, vv, o);
    float g = 2.f / vv;
    __syncwarp();

    // left: T[j+1.., c] -= g * v * (v^H T[j+1.., c]); rows striped by half
    {
      int c = l16;
      float2 s = make_float2(0.f, 0.f);
      for (int r = j+1; r < 16; r++) s = cadd(s, cmulj(T[r*MSTR + c], V[r]));
      float2 gs = cscale(s, g);
      __syncwarp();
      for (int r = j+1+half; r < 16; r += 2)
        T[r*MSTR + c] = csub(T[r*MSTR + c], cmul(V[r], gs));
    }
    __syncwarp();
    // right: half 0 -> T rows, half 1 -> Q rows (row-private)
    {
      int r = l16;
      float2* M = half ? Q : T;
      float2 s = make_float2(0.f, 0.f);
      for (int c = j+1; c < 16; c++) s = cadd(s, cmul(M[r*MSTR + c], V[c]));
      float2 gs = cscale(s, g);
      for (int c = j+1; c < 16; c++)
        M[r*MSTR + c] = csub(M[r*MSTR + c], cmulj(gs, V[c]));
    }
    __syncwarp();
  }

  // ---- shifted QR to Schur form ----
  const float EPSQ = 1e-5f;
  int hi = 15;
  int iter_at_hi = 0, total = 0;
  while (hi > 0 && total < 300) {
    // parallel deflation scan
    bool small = false;
    if (l16 >= 1 && l16 <= hi) {
      float sub = cabs1(T[l16*MSTR + (l16-1)]);
      float thr = EPSQ * (cabs1(T[(l16-1)*MSTR + (l16-1)]) + cabs1(T[l16*MSTR + l16])) + 1e-30f;
      small = (sub <= thr);
    }
    unsigned msk = __ballot_sync(FULLMASK, small) & 0xFFFFu;
    if (small && lane < 16) T[l16*MSTR + (l16-1)] = make_float2(0.f, 0.f);
    __syncwarp();
    int lo = msk ? (31 - __clz((int)msk)) : 0;
    if (lo == hi) { hi--; iter_at_hi = 0; continue; }
    iter_at_hi++; total++;

    // shift (uniform on all lanes)
    float2 tbb = T[hi*MSTR + hi];
    float2 mu;
    if (iter_at_hi % 8 == 0) {
      float es = cabs1(T[hi*MSTR + (hi-1)]);
      mu = make_float2(tbb.x + 0.75f*es, tbb.y);
    } else {
      float2 taa = T[(hi-1)*MSTR + (hi-1)];
      float2 tab = T[(hi-1)*MSTR + hi];
      float2 tba = T[hi*MSTR + (hi-1)];
      float2 p = cscale(csub(taa, tbb), 0.5f);
      float2 q = csqrtc(cadd(cmul(p, p), cmul(tab, tba)));
      float2 s1 = cadd(p, q), s2 = csub(p, q);
      float2 dd = (cabs2(s1) < cabs2(s2)) ? s1 : s2;
      mu = cadd(tbb, dd);
    }

    float2 ga = csub(T[lo*MSTR + lo], mu);
    float2 gb = T[(lo+1)*MSTR + lo];
    int nrot = hi - lo;
    for (int k = lo; k < hi; k++) {
      if (k > lo) { ga = T[k*MSTR + (k-1)]; gb = T[(k+1)*MSTR + (k-1)]; }
      float r2 = cabs2(ga) + cabs2(gb);
      float invr;
      if (r2 > 1e-37f) invr = rsqrtf(r2);
      else { ga = make_float2(1.f, 0.f); gb = make_float2(0.f, 0.f); invr = 1.f; }
      if (lane == 0) {
        rotG[k-lo] = make_float4(ga.x, ga.y, gb.x, gb.y);
        rotI[k-lo] = invr;
      }
      // left update: rows k (half0) / k+1 (half1), col = l16, shfl-exchange
      {
        int c = l16;
        float2 own = T[(k+half)*MSTR + c];
        float2 oth;
        oth.x = __shfl_xor_sync(FULLMASK, own.x, 16);
        oth.y = __shfl_xor_sync(FULLMASK, own.y, 16);
        float2 p  = half ? oth : own;   // row k
        float2 q2 = half ? own : oth;   // row k+1
        float2 outv;
        if (half == 0) outv = cscale(cadd(cmulj(p, ga), cmulj(q2, gb)), invr);
        else           outv = cscale(csub(cmul(ga, q2), cmul(gb, p)), invr);
        T[(k+half)*MSTR + c] = outv;
      }
      __syncwarp();
      // right update on T: cols k (half0) / k+1 (half1), row = l16
      {
        int r = l16;
        float2 own = T[r*MSTR + k + half];
        float2 oth;
        oth.x = __shfl_xor_sync(FULLMASK, own.x, 16);
        oth.y = __shfl_xor_sync(FULLMASK, own.y, 16);
        float2 u  = half ? oth : own;   // col k
        float2 v2 = half ? own : oth;   // col k+1
        float2 outv;
        if (half == 0) outv = cscale(cadd(cmul(u, ga), cmul(v2, gb)), invr);
        else           outv = cscale(csub(cmulj(v2, ga), cmulj(u, gb)), invr);
        T[r*MSTR + k + half] = outv;
      }
      __syncwarp();
    }
    // apply stored rotations to Q (register carry, row-private)
    if (lane < 16) {
      int r = l16;
      float2 u = Q[r*MSTR + lo];
      for (int kk = 0; kk < nrot; kk++) {
        float4 g4 = rotG[kk];
        float iv = rotI[kk];
        float2 ga2 = make_float2(g4.x, g4.y), gb2 = make_float2(g4.z, g4.w);
        float2 v2 = Q[r*MSTR + lo + kk + 1];
        Q[r*MSTR + lo + kk] = cscale(cadd(cmul(u, ga2), cmul(v2, gb2)), iv);
        u = cscale(csub(cmulj(v2, ga2), cmulj(u, gb2)), iv);
      }
      Q[r*MSTR + hi] = u;
    }
    __syncwarp();
  }
  __syncwarp();

  // ---- eigenvectors (lanes 0-15; lane k owns eigenvector k) ----
  if (lane < 16) {
    float2 lam = T[lane*MSTR + lane];
    for (int j2 = 0; j2 < 16; j2++)
      Y[j2*MSTR + lane] = make_float2((j2 == lane) ? 1.f : 0.f, 0.f);
    float lscale = cabs1(lam) + 1e-20f;
    for (int i = 14; i >= 0; i--) {
      if (lane > i) {
        float2 ssum = make_float2(0.f, 0.f);
        for (int j2 = i+1; j2 <= lane; j2++)
          ssum = cadd(ssum, cmul(T[i*MSTR + j2], Y[j2*MSTR + lane]));
        float2 den = csub(T[i*MSTR + i], lam);
        float dmin = 1.1920929e-07f * lscale;
        if (cabs2(den) < dmin*dmin) den = make_float2(dmin, 0.f);
        float2 val = cdivc(make_float2(-ssum.x, -ssum.y), den);
        if (cabs2(val) > 1e24f) {
          float scf = 1e-12f;
          for (int j2 = i+1; j2 <= lane; j2++) {
            float2 t2 = Y[j2*MSTR + lane];
            Y[j2*MSTR + lane] = cscale(t2, scf);
          }
          val = cscale(val, scf);
        }
        Y[i*MSTR + lane] = val;
      }
    }

    // v = Q * y  (only columns 0..k contribute), normalize
    float2 vout[16];
    float n2 = 0.f;
#pragma unroll
    for (int r = 0; r < 16; r++) {
      float2 acc = make_float2(0.f, 0.f);
      for (int j2 = 0; j2 <= lane; j2++)
        acc = cadd(acc, cmul(Q[r*MSTR + j2], Y[j2*MSTR + lane]));
      vout[r] = acc;
      n2 += cabs2(acc);
    }
    float invn = rsqrtf(fmaxf(n2, 1e-37f));

    // rank by |lambda| descending (ties: larger index first)
    float aw = cabs2(lam);
    int rank = 0;
    for (int j2 = 0; j2 < 16; j2++) {
      float awj = __shfl_sync(AMASK, aw, j2);
      if (awj > aw || (awj == aw && j2 > lane)) rank++;
    }
    if (rank >= MSRC) {
      float2* dst = g_Un + (size_t)b * (NNOISE*NANT) + (rank - MSRC) * NANT;
#pragma unroll
      for (int r = 0; r < 16; r++) dst[r] = cscale(vout[r], invn);
    }
  }
}

// =============================================================================
// K6: MUSIC spectrum. One block per batch element, block=128.
// =============================================================================
__global__ void spec_kernel() {
  int b = blockIdx.x;
  __shared__ float2 su[NNOISE * NANT];
  for (int i = threadIdx.x; i < NNOISE*NANT; i += blockDim.x)
    su[i] = g_Un[(size_t)b * (NNOISE*NANT) + i];
  __syncthreads();
  for (int a = threadIdx.x; a < NANG; a += blockDim.x) {
    float2 ca[16];
#pragma unroll
    for (int n = 0; n < 16; n++) ca[n] = g_CA[a*16 + n];
    float den = 0.f;
    for (int k = 0; k < NNOISE; k++) {
      float2 acc = make_float2(0.f, 0.f);
#pragma unroll
      for (int n = 0; n < 16; n++) acc = cadd(acc, cmul(ca[n], su[k*16 + n]));
      den += cabs2(acc);
    }
    g_spec[b*NANG + a] = 1.f / den;
  }
}

// =============================================================================
// K7: MLP head. One warp per batch element, fc1W staged in shared.
// =============================================================================
__global__ void __launch_bounds__(128) head_kernel(
    const float* __restrict__ fc1W, const float* __restrict__ fc1b,
    const float* __restrict__ fc2W, const float* __restrict__ fc2b,
    const float* __restrict__ fc3W, const float* __restrict__ fc3b,
    float* __restrict__ out) {
  __shared__ float w1s[32 * 361];   // [j][a], padded to 361
  for (int idx = threadIdx.x; idx < 32*NANG; idx += blockDim.x) {
    int j = idx / NANG, a = idx - j*NANG;
    w1s[j*361 + a] = fc1W[idx];
  }
  __syncthreads();

  int b = blockIdx.x * 4 + (threadIdx.x >> 5);
  int lane = threadIdx.x & 31;
  const float* sp = g_spec + (size_t)b * NANG;

  float acc = fc1b[lane];
  const float* wrow = w1s + lane*361;
  for (int a = 0; a < NANG; a++) acc += sp[a] * wrow[a];
  float h1 = fmaxf(acc, 0.f);

  float w2[32];
#pragma unroll
  for (int k = 0; k < 32; k++) w2[k] = fc2W[lane*32 + k];
  float b2 = fc2b[lane];

  float a2 = b2;
#pragma unroll
  for (int k = 0; k < 32; k++) a2 += w2[k] * __shfl_sync(FULLMASK, h1, k);
  float h2 = fmaxf(a2, 0.f);

  float a3 = b2;
#pragma unroll
  for (int k = 0; k < 32; k++) a3 += w2[k] * __shfl_sync(FULLMASK, h2, k);
  float h3 = fmaxf(a3, 0.f);

#pragma unroll
  for (int m = 0; m < MSRC; m++) {
    float p = fc3W[m*32 + lane] * h3;
    for (int o = 16; o; o >>= 1) p += __shfl_xor_sync(FULLMASK, p, o);
    if (lane == 0) out[b*MSRC + m] = p + fc3b[m];
  }
}

// =============================================================================
extern "C" void kernel_launch(void* const* d_in, const int* in_sizes, int n_in,
                              void* d_out, int out_size) {
  const float* Xr   = (const float*)d_in[0];
  const float* Xi   = (const float*)d_in[1];
  const float* bn_w = (const float*)d_in[2];
  const float* bn_b = (const float*)d_in[3];
  const float* Wih  = (const float*)d_in[4];
  const float* Whh  = (const float*)d_in[5];
  const float* bih  = (const float*)d_in[6];
  const float* bhh  = (const float*)d_in[7];
  const float* fcW  = (const float*)d_in[8];
  const float* fcb  = (const float*)d_in[9];
  const float* fc1W = (const float*)d_in[10];
  const float* fc1b = (const float*)d_in[11];
  const float* fc2W = (const float*)d_in[12];
  const float* fc2b = (const float*)d_in[13];
  const float* fc3W = (const float*)d_in[14];
  const float* fc3b = (const float*)d_in[15];
  float* out = (float*)d_out;

  bn_stats_kernel<<<TT, 256>>>(Xr, Xi, bn_w, bn_b);
  steer_kernel<<<(NANG*NANT + 255)/256, 256>>>();
  gru_kernel<<<B_SZ/4, 128>>>(Xr, Xi, Wih, Whh, bih, bhh);
  fc_rx_kernel<<<dim3(2,64), 256>>>(fcW, fcb);
  eig_kernel<<<B_SZ/4, 128>>>();
  spec_kernel<<<B_SZ, 128>>>();
  head_kernel<<<B_SZ/4, 128>>>(fc1W, fc1b, fc2W, fc2b, fc3W, fc3b, out);
}